// round 1
// baseline (speedup 1.0000x reference)
#include <cuda_runtime.h>
#include <math.h>

#define Bn 8
#define Tn 2048
#define Cn 1024
#define Hn 64

// Scratch for projected q,k,v (device globals: the sanctioned no-alloc scratch path)
__device__ float g_q[Bn * Tn * Hn];
__device__ float g_k[Bn * Tn * Hn];
__device__ float g_v[Bn * Tn * Hn];

// ---------------------------------------------------------------------------
// Kernel 1: QKV projection.  out[m, h] = x[m, :] @ W[:, h] + b[h]
// M = B*T = 16384, N = H = 64, K = C = 1024.
// Tiles: BM=64, BN=64, BK=16. 256 threads, each computes a 4x4 register tile.
// grid = (256, 3); blockIdx.y selects which of {q, k, v}.
// ---------------------------------------------------------------------------
__global__ __launch_bounds__(256) void qkv_kernel(
    const float* __restrict__ x,
    const float* __restrict__ Wk, const float* __restrict__ bk,
    const float* __restrict__ Wq, const float* __restrict__ bq,
    const float* __restrict__ Wv, const float* __restrict__ bv)
{
    __shared__ float xs[16][68];   // x tile transposed: [k][row], padded stride
    __shared__ float ws[16][64];   // W tile natural:    [k][col]

    const float* W;
    const float* bias;
    float* out;
    if (blockIdx.y == 0)      { W = Wq; bias = bq; out = g_q; }
    else if (blockIdx.y == 1) { W = Wk; bias = bk; out = g_k; }
    else                      { W = Wv; bias = bv; out = g_v; }

    const int t  = threadIdx.x;
    const int tx = t & 15;
    const int ty = t >> 4;
    const int m0 = blockIdx.x * 64;

    // load-role indices
    const int xr = t >> 2;          // 0..63 row within x tile
    const int xc = (t & 3) * 4;     // 0..12 col (float4) within BK=16
    const int wr = t >> 4;          // 0..15 row within W tile
    const int wc = (t & 15) * 4;    // 0..60 col (float4) within BN=64

    float acc[4][4] = {};

    for (int k0 = 0; k0 < Cn; k0 += 16) {
        float4 xv = *(const float4*)&x[(long)(m0 + xr) * Cn + k0 + xc];
        float4 wv = *(const float4*)&W[(long)(k0 + wr) * Hn + wc];
        __syncthreads();
        xs[xc + 0][xr] = xv.x;
        xs[xc + 1][xr] = xv.y;
        xs[xc + 2][xr] = xv.z;
        xs[xc + 3][xr] = xv.w;
        *(float4*)&ws[wr][wc] = wv;
        __syncthreads();

        #pragma unroll
        for (int kk = 0; kk < 16; kk++) {
            float4 a = *(float4*)&xs[kk][ty * 4];
            float4 b = *(float4*)&ws[kk][tx * 4];
            float ar[4] = {a.x, a.y, a.z, a.w};
            float br[4] = {b.x, b.y, b.z, b.w};
            #pragma unroll
            for (int i = 0; i < 4; i++)
                #pragma unroll
                for (int j = 0; j < 4; j++)
                    acc[i][j] += ar[i] * br[j];
        }
    }

    float4 bb = *(const float4*)&bias[tx * 4];
    #pragma unroll
    for (int i = 0; i < 4; i++) {
        float4 o;
        o.x = acc[i][0] + bb.x;
        o.y = acc[i][1] + bb.y;
        o.z = acc[i][2] + bb.z;
        o.w = acc[i][3] + bb.w;
        *(float4*)&out[(long)(m0 + ty * 4 + i) * Hn + tx * 4] = o;
    }
}

// ---------------------------------------------------------------------------
// Kernel 2: causal flash attention, fp32, online softmax.
// One CTA per (batch, 64-row q tile). 256 threads, 4x4 register tiles for
// both the S (=q k^T) and O (+= P v) GEMMs. P round-trips through smem.
// smem (dynamic, 68608 B): qs[64][68] (q^T), ks[64][68] (k^T),
//                          ps[64][68] (P^T), vs[64][64].
// ---------------------------------------------------------------------------
__global__ __launch_bounds__(256, 2) void attn_kernel(float* __restrict__ out)
{
    extern __shared__ float sm[];
    float* qs = sm;             // [h][row], stride 68
    float* ks = sm + 4352;      // [h][col], stride 68
    float* ps = sm + 8704;      // [col][row], stride 68
    float* vs = sm + 13056;     // [col][h], stride 64

    const int t  = threadIdx.x;
    const int tx = t & 15;
    const int ty = t >> 4;
    const int qi = blockIdx.x;          // q tile index, 0..31
    const int b  = blockIdx.y;
    const int q0 = qi * 64;
    const long base = (long)b * Tn * Hn;

    const int c0 = (t & 15) * 4;        // h offset for tile loads
    const int r0 = t >> 4;              // row offset (16 rows/pass, 4 passes)

    // Load q tile transposed into qs[h][row]
    #pragma unroll
    for (int it = 0; it < 4; it++) {
        int r = r0 + it * 16;
        float4 v = *(const float4*)&g_q[base + (long)(q0 + r) * Hn + c0];
        qs[(c0 + 0) * 68 + r] = v.x;
        qs[(c0 + 1) * 68 + r] = v.y;
        qs[(c0 + 2) * 68 + r] = v.z;
        qs[(c0 + 3) * 68 + r] = v.w;
    }

    float m_i[4], l_i[4], o[4][4];
    #pragma unroll
    for (int i = 0; i < 4; i++) {
        m_i[i] = -1e30f;
        l_i[i] = 0.0f;
        #pragma unroll
        for (int j = 0; j < 4; j++) o[i][j] = 0.0f;
    }

    const float scale = 0.03125f;   // C^-0.5 = 1024^-0.5

    for (int j = 0; j <= qi; j++) {
        const int k0 = j * 64;
        __syncthreads();   // prev PV done (and first iter: qs visible)

        // Load k tile transposed, v tile natural
        #pragma unroll
        for (int it = 0; it < 4; it++) {
            int r = r0 + it * 16;
            float4 kv = *(const float4*)&g_k[base + (long)(k0 + r) * Hn + c0];
            ks[(c0 + 0) * 68 + r] = kv.x;
            ks[(c0 + 1) * 68 + r] = kv.y;
            ks[(c0 + 2) * 68 + r] = kv.z;
            ks[(c0 + 3) * 68 + r] = kv.w;
            float4 vv = *(const float4*)&g_v[base + (long)(k0 + r) * Hn + c0];
            *(float4*)&vs[r * 64 + c0] = vv;
        }
        __syncthreads();

        // S = q @ k^T   (dot over h = 64)
        float s[4][4] = {};
        #pragma unroll 8
        for (int kk = 0; kk < 64; kk++) {
            float4 a = *(float4*)&qs[kk * 68 + ty * 4];
            float4 bq4 = *(float4*)&ks[kk * 68 + tx * 4];
            float ar[4] = {a.x, a.y, a.z, a.w};
            float br[4] = {bq4.x, bq4.y, bq4.z, bq4.w};
            #pragma unroll
            for (int i = 0; i < 4; i++)
                #pragma unroll
                for (int jj = 0; jj < 4; jj++)
                    s[i][jj] += ar[i] * br[jj];
        }

        // scale + causal mask (only on diagonal tile)
        #pragma unroll
        for (int i = 0; i < 4; i++)
            #pragma unroll
            for (int jj = 0; jj < 4; jj++) {
                s[i][jj] *= scale;
                if (j == qi && (tx * 4 + jj) > (ty * 4 + i))
                    s[i][jj] = -1e30f;
            }

        // online softmax: row max/sum via shuffle across the 16-lane tx group
        float p[4][4], mn[4], rs[4];
        #pragma unroll
        for (int i = 0; i < 4; i++) {
            float mt = s[i][0];
            mt = fmaxf(mt, s[i][1]);
            mt = fmaxf(mt, s[i][2]);
            mt = fmaxf(mt, s[i][3]);
            #pragma unroll
            for (int off = 8; off > 0; off >>= 1)
                mt = fmaxf(mt, __shfl_xor_sync(0xffffffffu, mt, off));
            mn[i] = fmaxf(m_i[i], mt);
            float r = 0.0f;
            #pragma unroll
            for (int jj = 0; jj < 4; jj++) {
                p[i][jj] = __expf(s[i][jj] - mn[i]);
                r += p[i][jj];
            }
            #pragma unroll
            for (int off = 8; off > 0; off >>= 1)
                r += __shfl_xor_sync(0xffffffffu, r, off);
            rs[i] = r;
        }
        #pragma unroll
        for (int i = 0; i < 4; i++) {
            float alpha = __expf(m_i[i] - mn[i]);
            l_i[i] = l_i[i] * alpha + rs[i];
            m_i[i] = mn[i];
            #pragma unroll
            for (int jj = 0; jj < 4; jj++) o[i][jj] *= alpha;
        }

        // write P transposed: ps[col][row], vectorized over rows
        #pragma unroll
        for (int jj = 0; jj < 4; jj++) {
            float4 pv = make_float4(p[0][jj], p[1][jj], p[2][jj], p[3][jj]);
            *(float4*)&ps[(tx * 4 + jj) * 68 + ty * 4] = pv;
        }
        __syncthreads();

        // O += P @ V   (sum over kpos = 64)
        #pragma unroll 8
        for (int kk = 0; kk < 64; kk++) {
            float4 pa = *(float4*)&ps[kk * 68 + ty * 4];
            float4 vb = *(float4*)&vs[kk * 64 + tx * 4];
            float pr[4] = {pa.x, pa.y, pa.z, pa.w};
            float vr[4] = {vb.x, vb.y, vb.z, vb.w};
            #pragma unroll
            for (int i = 0; i < 4; i++)
                #pragma unroll
                for (int jj = 0; jj < 4; jj++)
                    o[i][jj] += pr[i] * vr[jj];
        }
    }

    // normalize and store
    #pragma unroll
    for (int i = 0; i < 4; i++) {
        float inv = 1.0f / l_i[i];
        float4 ov;
        ov.x = o[i][0] * inv;
        ov.y = o[i][1] * inv;
        ov.z = o[i][2] * inv;
        ov.w = o[i][3] * inv;
        *(float4*)&out[base + (long)(q0 + ty * 4 + i) * Hn + tx * 4] = ov;
    }
}

// ---------------------------------------------------------------------------
extern "C" void kernel_launch(void* const* d_in, const int* in_sizes, int n_in,
                              void* d_out, int out_size)
{
    const float* x  = (const float*)d_in[0];
    const float* Wk = (const float*)d_in[1];
    const float* bk = (const float*)d_in[2];
    const float* Wq = (const float*)d_in[3];
    const float* bq = (const float*)d_in[4];
    const float* Wv = (const float*)d_in[5];
    const float* bv = (const float*)d_in[6];
    float* out = (float*)d_out;

    qkv_kernel<<<dim3((Bn * Tn) / 64, 3), 256>>>(x, Wk, bk, Wq, bq, Wv, bv);

    cudaFuncSetAttribute(attn_kernel,
                         cudaFuncAttributeMaxDynamicSharedMemorySize, 68608);
    attn_kernel<<<dim3(Tn / 64, Bn), 256, 68608>>>(out);
}

// round 3
// speedup vs baseline: 1.5928x; 1.5928x over previous
#include <cuda_runtime.h>
#include <cstdint>
#include <math.h>

#define Bn 8
#define Tn 2048
#define Cn 1024
#define Hn 64

// ---------------- device scratch (sanctioned no-alloc path) ----------------
__device__ float g_q[Bn * Tn * Hn];
__device__ float g_k[Bn * Tn * Hn];
__device__ float g_v[Bn * Tn * Hn];
// transposed + tf32-split weights: [o][n][k] (o = 0:q 1:k 2:v), flattened [192][1024]
__device__ float g_wt_hi[3 * Hn * Cn];
__device__ float g_wt_lo[3 * Hn * Cn];

__device__ __forceinline__ float tf32_round(float x) {
    uint32_t u;
    asm("cvt.rna.tf32.f32 %0, %1;" : "=r"(u) : "f"(x));
    return __uint_as_float(u);
}

// warp-level tf32 MMA, D = A(16x8) * B(8x8) + D  (sm_80+, safe on plain sm_100)
__device__ __forceinline__ void mma_tf32(float* c, const uint32_t* a, const uint32_t* b) {
    asm volatile(
        "mma.sync.aligned.m16n8k8.row.col.f32.tf32.tf32.f32 "
        "{%0,%1,%2,%3}, {%4,%5,%6,%7}, {%8,%9}, {%0,%1,%2,%3};"
        : "+f"(c[0]), "+f"(c[1]), "+f"(c[2]), "+f"(c[3])
        : "r"(a[0]), "r"(a[1]), "r"(a[2]), "r"(a[3]), "r"(b[0]), "r"(b[1]));
}

// ---------------------------------------------------------------------------
// prep: transpose weights to [o][n][k] and Dekker-split into tf32 hi/lo.
// ---------------------------------------------------------------------------
__global__ void prep_w(const float* __restrict__ Wk, const float* __restrict__ Wq,
                       const float* __restrict__ Wv) {
    int idx = blockIdx.x * 256 + threadIdx.x;            // [0, 3*64*1024)
    int o = idx / (Hn * Cn);
    int rem = idx - o * (Hn * Cn);
    int n = rem / Cn;
    int k = rem - n * Cn;
    const float* W = (o == 0) ? Wq : (o == 1) ? Wk : Wv;
    float v = W[k * Hn + n];
    float h = tf32_round(v);
    g_wt_hi[idx] = h;
    g_wt_lo[idx] = tf32_round(v - h);
}

// ---------------------------------------------------------------------------
// QKV via mma.sync tf32, 3-term split. CTA: 128 rows x 192 cols (q|k|v).
// 8 warps as 2(m) x 4(n): warp tile m64 x n48. K streamed in 32-chunks.
// smem (floats, stride 36 words -> conflict-free fragment loads):
//   Ah[128*36] Al[128*36] Bh[192*36] Bl[192*36]  = 92160 bytes
// ---------------------------------------------------------------------------
#define AST 36
#define QKV_SMEM (23040 * 4)

__global__ __launch_bounds__(256) void qkv_mma(
    const float* __restrict__ x,
    const float* __restrict__ bk, const float* __restrict__ bq, const float* __restrict__ bv)
{
    extern __shared__ float smf[];
    float* Ah = smf;
    float* Al = smf + 128 * AST;
    float* Bh = smf + 2 * 128 * AST;
    float* Bl = smf + 2 * 128 * AST + 192 * AST;

    const int t = threadIdx.x;
    const int wid = t >> 5, lane = t & 31;
    const int wm = wid >> 2, wn = wid & 3;       // warp grid 2 x 4
    const int g = lane >> 2, tg = lane & 3;      // quad row / thread-in-quad
    const int m0 = blockIdx.x * 128;

    float c[4][6][4];
    #pragma unroll
    for (int mf = 0; mf < 4; mf++)
        #pragma unroll
        for (int nf = 0; nf < 6; nf++)
            #pragma unroll
            for (int r = 0; r < 4; r++) c[mf][nf][r] = 0.0f;

    for (int ch = 0; ch < 32; ch++) {
        const int k0 = ch * 32;
        __syncthreads();
        // ---- A chunk: 128 x 32, split hi/lo ----
        #pragma unroll
        for (int i = 0; i < 4; i++) {
            int idx = t + i * 256;               // 0..1023
            int r = idx >> 3, c4 = idx & 7;
            float4 v = *(const float4*)&x[(size_t)(m0 + r) * Cn + k0 + c4 * 4];
            float4 h, l;
            h.x = tf32_round(v.x); l.x = tf32_round(v.x - h.x);
            h.y = tf32_round(v.y); l.y = tf32_round(v.y - h.y);
            h.z = tf32_round(v.z); l.z = tf32_round(v.z - h.z);
            h.w = tf32_round(v.w); l.w = tf32_round(v.w - h.w);
            *(float4*)&Ah[r * AST + c4 * 4] = h;
            *(float4*)&Al[r * AST + c4 * 4] = l;
        }
        // ---- B chunk: 192 x 32, hi & lo (pre-split in prep) ----
        #pragma unroll
        for (int i = 0; i < 6; i++) {
            int idx = t + i * 256;               // 0..1535
            int r = idx >> 3, c4 = idx & 7;
            *(float4*)&Bh[r * AST + c4 * 4] = *(const float4*)&g_wt_hi[(size_t)r * Cn + k0 + c4 * 4];
            *(float4*)&Bl[r * AST + c4 * 4] = *(const float4*)&g_wt_lo[(size_t)r * Cn + k0 + c4 * 4];
        }
        __syncthreads();

        #pragma unroll
        for (int ks = 0; ks < 4; ks++) {
            const int kk = ks * 8;
            uint32_t a_h[4][4], a_l[4][4], b_h[6][2], b_l[6][2];
            #pragma unroll
            for (int mf = 0; mf < 4; mf++) {
                int base = (wm * 64 + mf * 16 + g) * AST + kk + tg;
                a_h[mf][0] = __float_as_uint(Ah[base]);
                a_h[mf][1] = __float_as_uint(Ah[base + 8 * AST]);
                a_h[mf][2] = __float_as_uint(Ah[base + 4]);
                a_h[mf][3] = __float_as_uint(Ah[base + 8 * AST + 4]);
                a_l[mf][0] = __float_as_uint(Al[base]);
                a_l[mf][1] = __float_as_uint(Al[base + 8 * AST]);
                a_l[mf][2] = __float_as_uint(Al[base + 4]);
                a_l[mf][3] = __float_as_uint(Al[base + 8 * AST + 4]);
            }
            #pragma unroll
            for (int nf = 0; nf < 6; nf++) {
                int base = (wn * 48 + nf * 8 + g) * AST + kk + tg;
                b_h[nf][0] = __float_as_uint(Bh[base]);
                b_h[nf][1] = __float_as_uint(Bh[base + 4]);
                b_l[nf][0] = __float_as_uint(Bl[base]);
                b_l[nf][1] = __float_as_uint(Bl[base + 4]);
            }
            // term-major ordering: consecutive MMAs independent (24 chains)
            #pragma unroll
            for (int nf = 0; nf < 6; nf++)
                #pragma unroll
                for (int mf = 0; mf < 4; mf++)
                    mma_tf32(c[mf][nf], a_h[mf], b_h[nf]);
            #pragma unroll
            for (int nf = 0; nf < 6; nf++)
                #pragma unroll
                for (int mf = 0; mf < 4; mf++)
                    mma_tf32(c[mf][nf], a_h[mf], b_l[nf]);
            #pragma unroll
            for (int nf = 0; nf < 6; nf++)
                #pragma unroll
                for (int mf = 0; mf < 4; mf++)
                    mma_tf32(c[mf][nf], a_l[mf], b_h[nf]);
        }
    }

    // ---- epilogue: bias + direct float2 stores ----
    #pragma unroll
    for (int nf = 0; nf < 6; nf++) {
        int col = wn * 48 + nf * 8 + tg * 2;     // 0..190, even
        int o = col >> 6;
        int h = col & 63;
        float* gout = (o == 0) ? g_q : (o == 1) ? g_k : g_v;
        const float* bias = (o == 0) ? bq : (o == 1) ? bk : bv;
        float2 bb = *(const float2*)&bias[h];
        #pragma unroll
        for (int mf = 0; mf < 4; mf++) {
            int r0 = m0 + wm * 64 + mf * 16 + g;
            float2 v0 = make_float2(c[mf][nf][0] + bb.x, c[mf][nf][1] + bb.y);
            float2 v1 = make_float2(c[mf][nf][2] + bb.x, c[mf][nf][3] + bb.y);
            *(float2*)&gout[(size_t)r0 * Hn + h] = v0;
            *(float2*)&gout[(size_t)(r0 + 8) * Hn + h] = v1;
        }
    }
}

// ---------------------------------------------------------------------------
// Causal flash attention, fp32, online softmax. Balanced: CTA blockIdx.x
// handles q-tiles (bx, 31-bx) -> 128 CTAs of identical 33-iteration work.
// ---------------------------------------------------------------------------
__global__ __launch_bounds__(256, 2) void attn_kernel(float* __restrict__ out)
{
    extern __shared__ float smf[];
    float* qs = smf;             // [h][row], stride 68
    float* ks = smf + 4352;      // [h][col], stride 68
    float* ps = smf + 8704;      // [col][row], stride 68
    float* vs = smf + 13056;     // [col][h], stride 64

    const int t  = threadIdx.x;
    const int tx = t & 15;
    const int ty = t >> 4;
    const int b  = blockIdx.y;
    const long base = (long)b * Tn * Hn;
    const int c0 = (t & 15) * 4;
    const int r0 = t >> 4;
    const float scale = 0.03125f;   // 1024^-0.5

    for (int tloop = 0; tloop < 2; tloop++) {
        const int qi = (tloop == 0) ? blockIdx.x : (31 - blockIdx.x);
        const int q0 = qi * 64;

        #pragma unroll
        for (int it = 0; it < 4; it++) {
            int r = r0 + it * 16;
            float4 v = *(const float4*)&g_q[base + (long)(q0 + r) * Hn + c0];
            qs[(c0 + 0) * 68 + r] = v.x;
            qs[(c0 + 1) * 68 + r] = v.y;
            qs[(c0 + 2) * 68 + r] = v.z;
            qs[(c0 + 3) * 68 + r] = v.w;
        }

        float m_i[4], l_i[4], o[4][4];
        #pragma unroll
        for (int i = 0; i < 4; i++) {
            m_i[i] = -1e30f; l_i[i] = 0.0f;
            #pragma unroll
            for (int j = 0; j < 4; j++) o[i][j] = 0.0f;
        }

        for (int j = 0; j <= qi; j++) {
            const int k0 = j * 64;
            __syncthreads();

            #pragma unroll
            for (int it = 0; it < 4; it++) {
                int r = r0 + it * 16;
                float4 kv = *(const float4*)&g_k[base + (long)(k0 + r) * Hn + c0];
                ks[(c0 + 0) * 68 + r] = kv.x;
                ks[(c0 + 1) * 68 + r] = kv.y;
                ks[(c0 + 2) * 68 + r] = kv.z;
                ks[(c0 + 3) * 68 + r] = kv.w;
                float4 vv = *(const float4*)&g_v[base + (long)(k0 + r) * Hn + c0];
                *(float4*)&vs[r * 64 + c0] = vv;
            }
            __syncthreads();

            float s[4][4] = {};
            #pragma unroll 8
            for (int kk = 0; kk < 64; kk++) {
                float4 a = *(float4*)&qs[kk * 68 + ty * 4];
                float4 bq4 = *(float4*)&ks[kk * 68 + tx * 4];
                float ar[4] = {a.x, a.y, a.z, a.w};
                float br[4] = {bq4.x, bq4.y, bq4.z, bq4.w};
                #pragma unroll
                for (int i = 0; i < 4; i++)
                    #pragma unroll
                    for (int jj = 0; jj < 4; jj++)
                        s[i][jj] += ar[i] * br[jj];
            }

            #pragma unroll
            for (int i = 0; i < 4; i++)
                #pragma unroll
                for (int jj = 0; jj < 4; jj++) {
                    s[i][jj] *= scale;
                    if (j == qi && (tx * 4 + jj) > (ty * 4 + i))
                        s[i][jj] = -1e30f;
                }

            float p[4][4], mn[4], rs[4];
            #pragma unroll
            for (int i = 0; i < 4; i++) {
                float mt = fmaxf(fmaxf(s[i][0], s[i][1]), fmaxf(s[i][2], s[i][3]));
                #pragma unroll
                for (int off = 8; off > 0; off >>= 1)
                    mt = fmaxf(mt, __shfl_xor_sync(0xffffffffu, mt, off));
                mn[i] = fmaxf(m_i[i], mt);
                float r = 0.0f;
                #pragma unroll
                for (int jj = 0; jj < 4; jj++) {
                    p[i][jj] = __expf(s[i][jj] - mn[i]);
                    r += p[i][jj];
                }
                #pragma unroll
                for (int off = 8; off > 0; off >>= 1)
                    r += __shfl_xor_sync(0xffffffffu, r, off);
                rs[i] = r;
            }
            #pragma unroll
            for (int i = 0; i < 4; i++) {
                float alpha = __expf(m_i[i] - mn[i]);
                l_i[i] = l_i[i] * alpha + rs[i];
                m_i[i] = mn[i];
                #pragma unroll
                for (int jj = 0; jj < 4; jj++) o[i][jj] *= alpha;
            }

            #pragma unroll
            for (int jj = 0; jj < 4; jj++) {
                float4 pv = make_float4(p[0][jj], p[1][jj], p[2][jj], p[3][jj]);
                *(float4*)&ps[(tx * 4 + jj) * 68 + ty * 4] = pv;
            }
            __syncthreads();

            #pragma unroll 8
            for (int kk = 0; kk < 64; kk++) {
                float4 pa = *(float4*)&ps[kk * 68 + ty * 4];
                float4 vb = *(float4*)&vs[kk * 64 + tx * 4];
                float pr[4] = {pa.x, pa.y, pa.z, pa.w};
                float vr[4] = {vb.x, vb.y, vb.z, vb.w};
                #pragma unroll
                for (int i = 0; i < 4; i++)
                    #pragma unroll
                    for (int jj = 0; jj < 4; jj++)
                        o[i][jj] += pr[i] * vr[jj];
            }
        }

        #pragma unroll
        for (int i = 0; i < 4; i++) {
            float inv = 1.0f / l_i[i];
            float4 ov;
            ov.x = o[i][0] * inv;
            ov.y = o[i][1] * inv;
            ov.z = o[i][2] * inv;
            ov.w = o[i][3] * inv;
            *(float4*)&out[base + (long)(q0 + ty * 4 + i) * Hn + tx * 4] = ov;
        }
        __syncthreads();
    }
}

// ---------------------------------------------------------------------------
extern "C" void kernel_launch(void* const* d_in, const int* in_sizes, int n_in,
                              void* d_out, int out_size)
{
    const float* x  = (const float*)d_in[0];
    const float* Wk = (const float*)d_in[1];
    const float* bk = (const float*)d_in[2];
    const float* Wq = (const float*)d_in[3];
    const float* bq = (const float*)d_in[4];
    const float* Wv = (const float*)d_in[5];
    const float* bv = (const float*)d_in[6];
    float* out = (float*)d_out;

    prep_w<<<(3 * Hn * Cn) / 256, 256>>>(Wk, Wq, Wv);

    cudaFuncSetAttribute(qkv_mma, cudaFuncAttributeMaxDynamicSharedMemorySize, QKV_SMEM);
    qkv_mma<<<(Bn * Tn) / 128, 256, QKV_SMEM>>>(x, bk, bq, bv);

    cudaFuncSetAttribute(attn_kernel, cudaFuncAttributeMaxDynamicSharedMemorySize, 68608);
    attn_kernel<<<dim3(16, Bn), 256, 68608>>>(out);
}

// round 4
// speedup vs baseline: 2.2106x; 1.3879x over previous
#include <cuda_runtime.h>
#include <cstdint>
#include <math.h>

#define Bn 8
#define Tn 2048
#define Cn 1024
#define Hn 64

// ---------------- device scratch (sanctioned no-alloc path) ----------------
__device__ float g_q[Bn * Tn * Hn];
__device__ float g_k[Bn * Tn * Hn];
__device__ float g_v[Bn * Tn * Hn];
__device__ float g_wt_hi[3 * Hn * Cn];
__device__ float g_wt_lo[3 * Hn * Cn];

__device__ __forceinline__ float tf32_round(float x) {
    uint32_t u;
    asm("cvt.rna.tf32.f32 %0, %1;" : "=r"(u) : "f"(x));
    return __uint_as_float(u);
}

// warp-level tf32 MMA, D = A(16x8) * B(8x8) + D
// layouts (validated by R3 pass): a0=(g,tg) a1=(g+8,tg) a2=(g,tg+4) a3=(g+8,tg+4)
// b0=(k=tg,n=g) b1=(k=tg+4,n=g); c0=(g,2tg) c1=(g,2tg+1) c2=(g+8,2tg) c3=(g+8,2tg+1)
__device__ __forceinline__ void mma_tf32(float* c, const uint32_t* a, const uint32_t* b) {
    asm volatile(
        "mma.sync.aligned.m16n8k8.row.col.f32.tf32.tf32.f32 "
        "{%0,%1,%2,%3}, {%4,%5,%6,%7}, {%8,%9}, {%0,%1,%2,%3};"
        : "+f"(c[0]), "+f"(c[1]), "+f"(c[2]), "+f"(c[3])
        : "r"(a[0]), "r"(a[1]), "r"(a[2]), "r"(a[3]), "r"(b[0]), "r"(b[1]));
}

// ---------------------------------------------------------------------------
// prep: transpose weights to [o][n][k] and Dekker-split into tf32 hi/lo.
// ---------------------------------------------------------------------------
__global__ void prep_w(const float* __restrict__ Wk, const float* __restrict__ Wq,
                       const float* __restrict__ Wv) {
    int idx = blockIdx.x * 256 + threadIdx.x;
    int o = idx / (Hn * Cn);
    int rem = idx - o * (Hn * Cn);
    int n = rem / Cn;
    int k = rem - n * Cn;
    const float* W = (o == 0) ? Wq : (o == 1) ? Wk : Wv;
    float v = W[k * Hn + n];
    float h = tf32_round(v);
    g_wt_hi[idx] = h;
    g_wt_lo[idx] = tf32_round(v - h);
}

// ---------------------------------------------------------------------------
// QKV via mma.sync tf32, 3-term split (unchanged from R3 pass).
// ---------------------------------------------------------------------------
#define AST 36
#define QKV_SMEM (23040 * 4)

__global__ __launch_bounds__(256) void qkv_mma(
    const float* __restrict__ x,
    const float* __restrict__ bk, const float* __restrict__ bq, const float* __restrict__ bv)
{
    extern __shared__ float smf[];
    float* Ah = smf;
    float* Al = smf + 128 * AST;
    float* Bh = smf + 2 * 128 * AST;
    float* Bl = smf + 2 * 128 * AST + 192 * AST;

    const int t = threadIdx.x;
    const int wid = t >> 5, lane = t & 31;
    const int wm = wid >> 2, wn = wid & 3;
    const int g = lane >> 2, tg = lane & 3;
    const int m0 = blockIdx.x * 128;

    float c[4][6][4];
    #pragma unroll
    for (int mf = 0; mf < 4; mf++)
        #pragma unroll
        for (int nf = 0; nf < 6; nf++)
            #pragma unroll
            for (int r = 0; r < 4; r++) c[mf][nf][r] = 0.0f;

    for (int ch = 0; ch < 32; ch++) {
        const int k0 = ch * 32;
        __syncthreads();
        #pragma unroll
        for (int i = 0; i < 4; i++) {
            int idx = t + i * 256;
            int r = idx >> 3, c4 = idx & 7;
            float4 v = *(const float4*)&x[(size_t)(m0 + r) * Cn + k0 + c4 * 4];
            float4 h, l;
            h.x = tf32_round(v.x); l.x = tf32_round(v.x - h.x);
            h.y = tf32_round(v.y); l.y = tf32_round(v.y - h.y);
            h.z = tf32_round(v.z); l.z = tf32_round(v.z - h.z);
            h.w = tf32_round(v.w); l.w = tf32_round(v.w - h.w);
            *(float4*)&Ah[r * AST + c4 * 4] = h;
            *(float4*)&Al[r * AST + c4 * 4] = l;
        }
        #pragma unroll
        for (int i = 0; i < 6; i++) {
            int idx = t + i * 256;
            int r = idx >> 3, c4 = idx & 7;
            *(float4*)&Bh[r * AST + c4 * 4] = *(const float4*)&g_wt_hi[(size_t)r * Cn + k0 + c4 * 4];
            *(float4*)&Bl[r * AST + c4 * 4] = *(const float4*)&g_wt_lo[(size_t)r * Cn + k0 + c4 * 4];
        }
        __syncthreads();

        #pragma unroll
        for (int ks = 0; ks < 4; ks++) {
            const int kk = ks * 8;
            uint32_t a_h[4][4], a_l[4][4], b_h[6][2], b_l[6][2];
            #pragma unroll
            for (int mf = 0; mf < 4; mf++) {
                int base = (wm * 64 + mf * 16 + g) * AST + kk + tg;
                a_h[mf][0] = __float_as_uint(Ah[base]);
                a_h[mf][1] = __float_as_uint(Ah[base + 8 * AST]);
                a_h[mf][2] = __float_as_uint(Ah[base + 4]);
                a_h[mf][3] = __float_as_uint(Ah[base + 8 * AST + 4]);
                a_l[mf][0] = __float_as_uint(Al[base]);
                a_l[mf][1] = __float_as_uint(Al[base + 8 * AST]);
                a_l[mf][2] = __float_as_uint(Al[base + 4]);
                a_l[mf][3] = __float_as_uint(Al[base + 8 * AST + 4]);
            }
            #pragma unroll
            for (int nf = 0; nf < 6; nf++) {
                int base = (wn * 48 + nf * 8 + g) * AST + kk + tg;
                b_h[nf][0] = __float_as_uint(Bh[base]);
                b_h[nf][1] = __float_as_uint(Bh[base + 4]);
                b_l[nf][0] = __float_as_uint(Bl[base]);
                b_l[nf][1] = __float_as_uint(Bl[base + 4]);
            }
            #pragma unroll
            for (int nf = 0; nf < 6; nf++)
                #pragma unroll
                for (int mf = 0; mf < 4; mf++)
                    mma_tf32(c[mf][nf], a_h[mf], b_h[nf]);
            #pragma unroll
            for (int nf = 0; nf < 6; nf++)
                #pragma unroll
                for (int mf = 0; mf < 4; mf++)
                    mma_tf32(c[mf][nf], a_h[mf], b_l[nf]);
            #pragma unroll
            for (int nf = 0; nf < 6; nf++)
                #pragma unroll
                for (int mf = 0; mf < 4; mf++)
                    mma_tf32(c[mf][nf], a_l[mf], b_h[nf]);
        }
    }

    #pragma unroll
    for (int nf = 0; nf < 6; nf++) {
        int col = wn * 48 + nf * 8 + tg * 2;
        int o = col >> 6;
        int h = col & 63;
        float* gout = (o == 0) ? g_q : (o == 1) ? g_k : g_v;
        const float* bias = (o == 0) ? bq : (o == 1) ? bk : bv;
        float2 bb = *(const float2*)&bias[h];
        #pragma unroll
        for (int mf = 0; mf < 4; mf++) {
            int r0 = m0 + wm * 64 + mf * 16 + g;
            float2 v0 = make_float2(c[mf][nf][0] + bb.x, c[mf][nf][1] + bb.y);
            float2 v1 = make_float2(c[mf][nf][2] + bb.x, c[mf][nf][3] + bb.y);
            *(float2*)&gout[(size_t)r0 * Hn + h] = v0;
            *(float2*)&gout[(size_t)(r0 + 8) * Hn + h] = v1;
        }
    }
}

// ---------------------------------------------------------------------------
// Flash attention on mma.sync tf32. CTA: 64 q-rows, 4 warps (16 rows each),
// balanced pairs (bx, 31-bx). S plain tf32; PV 3-term split.
// smem (floats): ks[64][68], vh[64][72], vl[64][72], ph[64][68], pl[64][68]
// = 22272 floats = 89088 B; 2 CTAs/SM.
// ---------------------------------------------------------------------------
#define KST 68
#define VST 72
#define ATTN_SMEM (22272 * 4)

__global__ __launch_bounds__(128, 2) void attn_mma(float* __restrict__ out)
{
    extern __shared__ float smf[];
    float* ksm = smf;                 // K tile [kpos][h]
    float* vh  = smf + 4352;          // V hi  [kpos][h]
    float* vl  = smf + 8960;          // V lo
    float* ph  = smf + 13568;         // P hi  [qrow][kpos]
    float* pl  = smf + 17920;         // P lo

    const int t = threadIdx.x;
    const int w = t >> 5, lane = t & 31;
    const int g = lane >> 2, tg = lane & 3;
    const int b = blockIdx.y;
    const long base = (long)b * Tn * Hn;
    const float scale = 0.03125f;     // 1024^-0.5

    for (int tloop = 0; tloop < 2; tloop++) {
        const int qi = (tloop == 0) ? blockIdx.x : (31 - blockIdx.x);
        const int q0 = qi * 64;
        const int rw = w * 16 + g;    // local q row (thread's first row)

        // Q fragments in registers: pre-scaled, tf32.
        uint32_t qa[8][4];
        {
            const float* qp = &g_q[base + (long)(q0 + rw) * Hn];
            #pragma unroll
            for (int ksi = 0; ksi < 8; ksi++) {
                qa[ksi][0] = __float_as_uint(tf32_round(qp[ksi * 8 + tg] * scale));
                qa[ksi][1] = __float_as_uint(tf32_round(qp[8 * Hn + ksi * 8 + tg] * scale));
                qa[ksi][2] = __float_as_uint(tf32_round(qp[ksi * 8 + tg + 4] * scale));
                qa[ksi][3] = __float_as_uint(tf32_round(qp[8 * Hn + ksi * 8 + tg + 4] * scale));
            }
        }

        float m0 = -1e30f, m1 = -1e30f, l0 = 0.0f, l1 = 0.0f;
        float o[8][4];
        #pragma unroll
        for (int nf = 0; nf < 8; nf++)
            #pragma unroll
            for (int r = 0; r < 4; r++) o[nf][r] = 0.0f;

        for (int j = 0; j <= qi; j++) {
            const int k0 = j * 64;
            __syncthreads();
            // load K (tf32) and V (split) tiles: 64x64 each
            #pragma unroll
            for (int i = 0; i < 8; i++) {
                int idx = t + i * 128;           // 0..1023
                int r = idx >> 4, c4 = (idx & 15) * 4;
                float4 kv = *(const float4*)&g_k[base + (long)(k0 + r) * Hn + c4];
                kv.x = tf32_round(kv.x); kv.y = tf32_round(kv.y);
                kv.z = tf32_round(kv.z); kv.w = tf32_round(kv.w);
                *(float4*)&ksm[r * KST + c4] = kv;
                float4 vv = *(const float4*)&g_v[base + (long)(k0 + r) * Hn + c4];
                float4 h, l;
                h.x = tf32_round(vv.x); l.x = tf32_round(vv.x - h.x);
                h.y = tf32_round(vv.y); l.y = tf32_round(vv.y - h.y);
                h.z = tf32_round(vv.z); l.z = tf32_round(vv.z - h.z);
                h.w = tf32_round(vv.w); l.w = tf32_round(vv.w - h.w);
                *(float4*)&vh[r * VST + c4] = h;
                *(float4*)&vl[r * VST + c4] = l;
            }
            __syncthreads();

            // ---- S = Qs . K^T  (m16 x n64 per warp) ----
            float s[8][4];
            #pragma unroll
            for (int nf = 0; nf < 8; nf++)
                #pragma unroll
                for (int r = 0; r < 4; r++) s[nf][r] = 0.0f;

            #pragma unroll
            for (int ksi = 0; ksi < 8; ksi++) {
                uint32_t bf[8][2];
                #pragma unroll
                for (int nf = 0; nf < 8; nf++) {
                    int a = (nf * 8 + g) * KST + ksi * 8 + tg;
                    bf[nf][0] = __float_as_uint(ksm[a]);
                    bf[nf][1] = __float_as_uint(ksm[a + 4]);
                }
                #pragma unroll
                for (int nf = 0; nf < 8; nf++)
                    mma_tf32(s[nf], qa[ksi], bf[nf]);
            }

            // ---- causal mask on diagonal tile ----
            if (j == qi) {
                #pragma unroll
                for (int nf = 0; nf < 8; nf++) {
                    int col = nf * 8 + 2 * tg;
                    if (col     > rw)     s[nf][0] = -1e30f;
                    if (col + 1 > rw)     s[nf][1] = -1e30f;
                    if (col     > rw + 8) s[nf][2] = -1e30f;
                    if (col + 1 > rw + 8) s[nf][3] = -1e30f;
                }
            }

            // ---- online softmax (rows g and g+8) ----
            float mx0 = -1e30f, mx1 = -1e30f;
            #pragma unroll
            for (int nf = 0; nf < 8; nf++) {
                mx0 = fmaxf(mx0, fmaxf(s[nf][0], s[nf][1]));
                mx1 = fmaxf(mx1, fmaxf(s[nf][2], s[nf][3]));
            }
            #pragma unroll
            for (int off = 1; off <= 2; off <<= 1) {
                mx0 = fmaxf(mx0, __shfl_xor_sync(0xffffffffu, mx0, off));
                mx1 = fmaxf(mx1, __shfl_xor_sync(0xffffffffu, mx1, off));
            }
            float mn0 = fmaxf(m0, mx0), mn1 = fmaxf(m1, mx1);
            float rs0 = 0.0f, rs1 = 0.0f;
            #pragma unroll
            for (int nf = 0; nf < 8; nf++) {
                s[nf][0] = __expf(s[nf][0] - mn0);
                s[nf][1] = __expf(s[nf][1] - mn0);
                s[nf][2] = __expf(s[nf][2] - mn1);
                s[nf][3] = __expf(s[nf][3] - mn1);
                rs0 += s[nf][0] + s[nf][1];
                rs1 += s[nf][2] + s[nf][3];
            }
            #pragma unroll
            for (int off = 1; off <= 2; off <<= 1) {
                rs0 += __shfl_xor_sync(0xffffffffu, rs0, off);
                rs1 += __shfl_xor_sync(0xffffffffu, rs1, off);
            }
            float a0 = __expf(m0 - mn0), a1 = __expf(m1 - mn1);
            l0 = l0 * a0 + rs0; m0 = mn0;
            l1 = l1 * a1 + rs1; m1 = mn1;
            #pragma unroll
            for (int nf = 0; nf < 8; nf++) {
                o[nf][0] *= a0; o[nf][1] *= a0;
                o[nf][2] *= a1; o[nf][3] *= a1;
            }

            // ---- stage P split to smem (per-warp region) ----
            #pragma unroll
            for (int nf = 0; nf < 8; nf++) {
                int col = nf * 8 + 2 * tg;
                float h0 = tf32_round(s[nf][0]);
                float h1 = tf32_round(s[nf][1]);
                float h2 = tf32_round(s[nf][2]);
                float h3 = tf32_round(s[nf][3]);
                *(float2*)&ph[rw * KST + col]       = make_float2(h0, h1);
                *(float2*)&ph[(rw + 8) * KST + col] = make_float2(h2, h3);
                *(float2*)&pl[rw * KST + col]       = make_float2(tf32_round(s[nf][0] - h0), tf32_round(s[nf][1] - h1));
                *(float2*)&pl[(rw + 8) * KST + col] = make_float2(tf32_round(s[nf][2] - h2), tf32_round(s[nf][3] - h3));
            }
            __syncwarp();

            // ---- O += P . V  (3-term split) ----
            #pragma unroll
            for (int ksi = 0; ksi < 8; ksi++) {
                uint32_t ah[4], al[4];
                {
                    int a = rw * KST + ksi * 8 + tg;
                    ah[0] = __float_as_uint(ph[a]);
                    ah[1] = __float_as_uint(ph[a + 8 * KST]);
                    ah[2] = __float_as_uint(ph[a + 4]);
                    ah[3] = __float_as_uint(ph[a + 8 * KST + 4]);
                    al[0] = __float_as_uint(pl[a]);
                    al[1] = __float_as_uint(pl[a + 8 * KST]);
                    al[2] = __float_as_uint(pl[a + 4]);
                    al[3] = __float_as_uint(pl[a + 8 * KST + 4]);
                }
                uint32_t bh[8][2], bl[8][2];
                #pragma unroll
                for (int nf = 0; nf < 8; nf++) {
                    int a = (ksi * 8 + tg) * VST + nf * 8 + g;
                    bh[nf][0] = __float_as_uint(vh[a]);
                    bh[nf][1] = __float_as_uint(vh[a + 4 * VST]);
                    bl[nf][0] = __float_as_uint(vl[a]);
                    bl[nf][1] = __float_as_uint(vl[a + 4 * VST]);
                }
                #pragma unroll
                for (int nf = 0; nf < 8; nf++)
                    mma_tf32(o[nf], ah, bh[nf]);
                #pragma unroll
                for (int nf = 0; nf < 8; nf++)
                    mma_tf32(o[nf], ah, bl[nf]);
                #pragma unroll
                for (int nf = 0; nf < 8; nf++)
                    mma_tf32(o[nf], al, bh[nf]);
            }
        }

        // ---- epilogue ----
        float inv0 = 1.0f / l0, inv1 = 1.0f / l1;
        #pragma unroll
        for (int nf = 0; nf < 8; nf++) {
            int col = nf * 8 + 2 * tg;
            long r0 = base + (long)(q0 + rw) * Hn + col;
            *(float2*)&out[r0]            = make_float2(o[nf][0] * inv0, o[nf][1] * inv0);
            *(float2*)&out[r0 + 8 * Hn]   = make_float2(o[nf][2] * inv1, o[nf][3] * inv1);
        }
        __syncthreads();
    }
}

// ---------------------------------------------------------------------------
extern "C" void kernel_launch(void* const* d_in, const int* in_sizes, int n_in,
                              void* d_out, int out_size)
{
    const float* x  = (const float*)d_in[0];
    const float* Wk = (const float*)d_in[1];
    const float* bk = (const float*)d_in[2];
    const float* Wq = (const float*)d_in[3];
    const float* bq = (const float*)d_in[4];
    const float* Wv = (const float*)d_in[5];
    const float* bv = (const float*)d_in[6];
    float* out = (float*)d_out;

    prep_w<<<(3 * Hn * Cn) / 256, 256>>>(Wk, Wq, Wv);

    cudaFuncSetAttribute(qkv_mma, cudaFuncAttributeMaxDynamicSharedMemorySize, QKV_SMEM);
    qkv_mma<<<(Bn * Tn) / 128, 256, QKV_SMEM>>>(x, bk, bq, bv);

    cudaFuncSetAttribute(attn_mma, cudaFuncAttributeMaxDynamicSharedMemorySize, ATTN_SMEM);
    attn_mma<<<dim3(16, Bn), 128, ATTN_SMEM>>>(out);
}

// round 7
// speedup vs baseline: 2.4836x; 1.1235x over previous
#include <cuda_runtime.h>
#include <cstdint>
#include <math.h>

#define Bn 8
#define Tn 2048
#define Cn 1024
#define Hn 64

// ---------------- device scratch (sanctioned no-alloc path) ----------------
__device__ float g_q[Bn * Tn * Hn];
__device__ float g_k[Bn * Tn * Hn];
__device__ float g_vh[Bn * Tn * Hn];   // V pre-split tf32 hi
__device__ float g_vl[Bn * Tn * Hn];   // V pre-split tf32 lo
__device__ float g_wt_hi[3 * Hn * Cn];
__device__ float g_wt_lo[3 * Hn * Cn];

__device__ __forceinline__ float tf32_round(float x) {
    uint32_t u;
    asm("cvt.rna.tf32.f32 %0, %1;" : "=r"(u) : "f"(x));
    return __uint_as_float(u);
}
__device__ __forceinline__ uint32_t smem_u32(const void* p) {
    uint32_t a;
    asm("{ .reg .u64 t; cvta.to.shared.u64 t, %1; cvt.u32.u64 %0, t; }" : "=r"(a) : "l"(p));
    return a;
}
__device__ __forceinline__ void cp16(uint32_t s, const void* g) {
    asm volatile("cp.async.cg.shared.global [%0], [%1], 16;" :: "r"(s), "l"(g));
}
#define CP_COMMIT() asm volatile("cp.async.commit_group;" ::: "memory")
#define CP_WAIT1()  asm volatile("cp.async.wait_group 1;" ::: "memory")
#define CP_WAIT0()  asm volatile("cp.async.wait_group 0;" ::: "memory")

// warp-level tf32 MMA, D = A(16x8) * B(8x8) + D   (layouts validated R3/R4)
__device__ __forceinline__ void mma_tf32(float* c, const uint32_t* a, const uint32_t* b) {
    asm volatile(
        "mma.sync.aligned.m16n8k8.row.col.f32.tf32.tf32.f32 "
        "{%0,%1,%2,%3}, {%4,%5,%6,%7}, {%8,%9}, {%0,%1,%2,%3};"
        : "+f"(c[0]), "+f"(c[1]), "+f"(c[2]), "+f"(c[3])
        : "r"(a[0]), "r"(a[1]), "r"(a[2]), "r"(a[3]), "r"(b[0]), "r"(b[1]));
}

// ---------------------------------------------------------------------------
// prep: transpose weights to [o][n][k] and Dekker-split into tf32 hi/lo.
// ---------------------------------------------------------------------------
__global__ void prep_w(const float* __restrict__ Wk, const float* __restrict__ Wq,
                       const float* __restrict__ Wv) {
    int idx = blockIdx.x * 256 + threadIdx.x;
    int o = idx / (Hn * Cn);
    int rem = idx - o * (Hn * Cn);
    int n = rem / Cn;
    int k = rem - n * Cn;
    const float* W = (o == 0) ? Wq : (o == 1) ? Wk : Wv;
    float v = W[k * Hn + n];
    float h = tf32_round(v);
    g_wt_hi[idx] = h;
    g_wt_lo[idx] = tf32_round(v - h);
}

// ---------------------------------------------------------------------------
// QKV via mma.sync tf32, 3-term split, cp.async double-buffered.
// Stage: A raw 128x36, Bh 192x36, Bl 192x36 = 18432 floats; x2 = 147456 B.
// ---------------------------------------------------------------------------
#define AST 36
#define QKV_STAGE_F 18432
#define QKV_SMEM (2 * QKV_STAGE_F * 4)

__global__ __launch_bounds__(256) void qkv_mma(
    const float* __restrict__ x,
    const float* __restrict__ bk, const float* __restrict__ bq, const float* __restrict__ bv)
{
    extern __shared__ float smf[];
    const uint32_t sb = smem_u32(smf);
    const int t = threadIdx.x;
    const int wid = t >> 5, lane = t & 31;
    const int wm = wid >> 2, wn = wid & 3;
    const int g = lane >> 2, tg = lane & 3;
    const int m0 = blockIdx.x * 128;

    const int ar = t >> 3, ac4 = (t & 7) * 4;

    float c[4][6][4];
    #pragma unroll
    for (int mf = 0; mf < 4; mf++)
        #pragma unroll
        for (int nf = 0; nf < 6; nf++)
            #pragma unroll
            for (int r = 0; r < 4; r++) c[mf][nf][r] = 0.0f;

    auto issue = [&](int ch, int st) {
        const int k0 = ch * 32;
        uint32_t sA = sb + (uint32_t)st * QKV_STAGE_F * 4;
        uint32_t sBh = sA + 128 * AST * 4;
        uint32_t sBl = sBh + 192 * AST * 4;
        #pragma unroll
        for (int i = 0; i < 4; i++) {
            int r = ar + i * 32;
            cp16(sA + (r * AST + ac4) * 4, &x[(size_t)(m0 + r) * Cn + k0 + ac4]);
        }
        #pragma unroll
        for (int i = 0; i < 6; i++) {
            int r = ar + i * 32;
            cp16(sBh + (r * AST + ac4) * 4, &g_wt_hi[(size_t)r * Cn + k0 + ac4]);
            cp16(sBl + (r * AST + ac4) * 4, &g_wt_lo[(size_t)r * Cn + k0 + ac4]);
        }
    };

    issue(0, 0);
    CP_COMMIT();

    for (int ch = 0; ch < 32; ch++) {
        if (ch < 31) { issue(ch + 1, (ch + 1) & 1); CP_COMMIT(); CP_WAIT1(); }
        else         { CP_WAIT0(); }
        __syncthreads();

        float* As = smf + (ch & 1) * QKV_STAGE_F;
        float* Bh = As + 128 * AST;
        float* Bl = Bh + 192 * AST;

        #pragma unroll
        for (int ks = 0; ks < 4; ks++) {
            const int kk = ks * 8;
            uint32_t a_h[4][4], a_l[4][4], b_h[6][2], b_l[6][2];
            #pragma unroll
            for (int mf = 0; mf < 4; mf++) {
                int base = (wm * 64 + mf * 16 + g) * AST + kk + tg;
                float r0 = As[base];
                float r1 = As[base + 8 * AST];
                float r2 = As[base + 4];
                float r3 = As[base + 8 * AST + 4];
                float h0 = tf32_round(r0), h1 = tf32_round(r1);
                float h2 = tf32_round(r2), h3 = tf32_round(r3);
                a_h[mf][0] = __float_as_uint(h0);
                a_h[mf][1] = __float_as_uint(h1);
                a_h[mf][2] = __float_as_uint(h2);
                a_h[mf][3] = __float_as_uint(h3);
                a_l[mf][0] = __float_as_uint(tf32_round(r0 - h0));
                a_l[mf][1] = __float_as_uint(tf32_round(r1 - h1));
                a_l[mf][2] = __float_as_uint(tf32_round(r2 - h2));
                a_l[mf][3] = __float_as_uint(tf32_round(r3 - h3));
            }
            #pragma unroll
            for (int nf = 0; nf < 6; nf++) {
                int base = (wn * 48 + nf * 8 + g) * AST + kk + tg;
                b_h[nf][0] = __float_as_uint(Bh[base]);
                b_h[nf][1] = __float_as_uint(Bh[base + 4]);
                b_l[nf][0] = __float_as_uint(Bl[base]);
                b_l[nf][1] = __float_as_uint(Bl[base + 4]);
            }
            #pragma unroll
            for (int nf = 0; nf < 6; nf++)
                #pragma unroll
                for (int mf = 0; mf < 4; mf++)
                    mma_tf32(c[mf][nf], a_h[mf], b_h[nf]);
            #pragma unroll
            for (int nf = 0; nf < 6; nf++)
                #pragma unroll
                for (int mf = 0; mf < 4; mf++)
                    mma_tf32(c[mf][nf], a_h[mf], b_l[nf]);
            #pragma unroll
            for (int nf = 0; nf < 6; nf++)
                #pragma unroll
                for (int mf = 0; mf < 4; mf++)
                    mma_tf32(c[mf][nf], a_l[mf], b_h[nf]);
        }
        __syncthreads();
    }

    // epilogue: bias; V written pre-split (tf32 hi/lo)
    #pragma unroll
    for (int nf = 0; nf < 6; nf++) {
        int col = wn * 48 + nf * 8 + tg * 2;
        int o = col >> 6;
        int h = col & 63;
        const float* bias = (o == 0) ? bq : (o == 1) ? bk : bv;
        float2 bb = *(const float2*)&bias[h];
        #pragma unroll
        for (int mf = 0; mf < 4; mf++) {
            int r0 = m0 + wm * 64 + mf * 16 + g;
            float v00 = c[mf][nf][0] + bb.x, v01 = c[mf][nf][1] + bb.y;
            float v10 = c[mf][nf][2] + bb.x, v11 = c[mf][nf][3] + bb.y;
            if (o < 2) {
                float* gout = (o == 0) ? g_q : g_k;
                *(float2*)&gout[(size_t)r0 * Hn + h] = make_float2(v00, v01);
                *(float2*)&gout[(size_t)(r0 + 8) * Hn + h] = make_float2(v10, v11);
            } else {
                float h00 = tf32_round(v00), h01 = tf32_round(v01);
                float h10 = tf32_round(v10), h11 = tf32_round(v11);
                *(float2*)&g_vh[(size_t)r0 * Hn + h] = make_float2(h00, h01);
                *(float2*)&g_vh[(size_t)(r0 + 8) * Hn + h] = make_float2(h10, h11);
                *(float2*)&g_vl[(size_t)r0 * Hn + h] =
                    make_float2(tf32_round(v00 - h00), tf32_round(v01 - h01));
                *(float2*)&g_vl[(size_t)(r0 + 8) * Hn + h] =
                    make_float2(tf32_round(v10 - h10), tf32_round(v11 - h11));
            }
        }
    }
}

// ---------------------------------------------------------------------------
// Flash attention, mma.sync tf32, cp.async double-buffered K/Vh/Vl,
// P passed via quad shuffles (no smem staging). 2 CTAs/SM.
// Stage: K 64x68 + Vh 64x72 + Vl 64x72 = 13568 floats = 54272 B; x2 = 108544 B.
// ---------------------------------------------------------------------------
#define KST 68
#define VST 72
#define ATT_STAGE_F 13568
#define ATTN_SMEM (2 * ATT_STAGE_F * 4)

__global__ __launch_bounds__(128, 2) void attn_mma(float* __restrict__ out)
{
    extern __shared__ float smf[];
    const uint32_t sb = smem_u32(smf);

    const int t = threadIdx.x;
    const int w = t >> 5, lane = t & 31;
    const int g = lane >> 2, tg = lane & 3;
    const int b = blockIdx.y;
    const long base = (long)b * Tn * Hn;
    const float scale = 0.03125f;     // 1024^-0.5

    const int lr = t >> 4, lc4 = (t & 15) * 4;

    auto issue = [&](int k0, int st) {
        uint32_t sK = sb + (uint32_t)st * ATT_STAGE_F * 4;
        uint32_t sVh = sK + 64 * KST * 4;
        uint32_t sVl = sVh + 64 * VST * 4;
        #pragma unroll
        for (int i = 0; i < 8; i++) {
            int r = lr + i * 8;
            cp16(sK + (r * KST + lc4) * 4, &g_k[base + (long)(k0 + r) * Hn + lc4]);
            cp16(sVh + (r * VST + lc4) * 4, &g_vh[base + (long)(k0 + r) * Hn + lc4]);
            cp16(sVl + (r * VST + lc4) * 4, &g_vl[base + (long)(k0 + r) * Hn + lc4]);
        }
    };

    for (int tloop = 0; tloop < 2; tloop++) {
        const int qi = (tloop == 0) ? blockIdx.x : (31 - blockIdx.x);
        const int q0 = qi * 64;
        const int rw = w * 16 + g;

        issue(0, 0);
        CP_COMMIT();

        uint32_t qa[8][4];
        {
            const float* qp = &g_q[base + (long)(q0 + rw) * Hn];
            #pragma unroll
            for (int ksi = 0; ksi < 8; ksi++) {
                qa[ksi][0] = __float_as_uint(tf32_round(qp[ksi * 8 + tg] * scale));
                qa[ksi][1] = __float_as_uint(tf32_round(qp[8 * Hn + ksi * 8 + tg] * scale));
                qa[ksi][2] = __float_as_uint(tf32_round(qp[ksi * 8 + tg + 4] * scale));
                qa[ksi][3] = __float_as_uint(tf32_round(qp[8 * Hn + ksi * 8 + tg + 4] * scale));
            }
        }

        float m0 = -1e30f, m1 = -1e30f, l0 = 0.0f, l1 = 0.0f;
        float o[8][4];
        #pragma unroll
        for (int nf = 0; nf < 8; nf++)
            #pragma unroll
            for (int r = 0; r < 4; r++) o[nf][r] = 0.0f;

        for (int j = 0; j <= qi; j++) {
            if (j < qi) { issue((j + 1) * 64, (j + 1) & 1); CP_COMMIT(); CP_WAIT1(); }
            else        { CP_WAIT0(); }
            __syncthreads();

            float* ksm = smf + (j & 1) * ATT_STAGE_F;
            float* vh = ksm + 64 * KST;
            float* vl = vh + 64 * VST;

            // ---- S = Qs . K^T ----
            float s[8][4];
            #pragma unroll
            for (int nf = 0; nf < 8; nf++)
                #pragma unroll
                for (int r = 0; r < 4; r++) s[nf][r] = 0.0f;

            #pragma unroll
            for (int ksi = 0; ksi < 8; ksi++) {
                uint32_t bf[8][2];
                #pragma unroll
                for (int nf = 0; nf < 8; nf++) {
                    int a = (nf * 8 + g) * KST + ksi * 8 + tg;
                    bf[nf][0] = __float_as_uint(ksm[a]);
                    bf[nf][1] = __float_as_uint(ksm[a + 4]);
                }
                #pragma unroll
                for (int nf = 0; nf < 8; nf++)
                    mma_tf32(s[nf], qa[ksi], bf[nf]);
            }

            if (j == qi) {
                #pragma unroll
                for (int nf = 0; nf < 8; nf++) {
                    int col = nf * 8 + 2 * tg;
                    if (col     > rw)     s[nf][0] = -1e30f;
                    if (col + 1 > rw)     s[nf][1] = -1e30f;
                    if (col     > rw + 8) s[nf][2] = -1e30f;
                    if (col + 1 > rw + 8) s[nf][3] = -1e30f;
                }
            }

            float mx0 = -1e30f, mx1 = -1e30f;
            #pragma unroll
            for (int nf = 0; nf < 8; nf++) {
                mx0 = fmaxf(mx0, fmaxf(s[nf][0], s[nf][1]));
                mx1 = fmaxf(mx1, fmaxf(s[nf][2], s[nf][3]));
            }
            #pragma unroll
            for (int off = 1; off <= 2; off <<= 1) {
                mx0 = fmaxf(mx0, __shfl_xor_sync(0xffffffffu, mx0, off));
                mx1 = fmaxf(mx1, __shfl_xor_sync(0xffffffffu, mx1, off));
            }
            float mn0 = fmaxf(m0, mx0), mn1 = fmaxf(m1, mx1);
            float rs0 = 0.0f, rs1 = 0.0f;
            #pragma unroll
            for (int nf = 0; nf < 8; nf++) {
                s[nf][0] = __expf(s[nf][0] - mn0);
                s[nf][1] = __expf(s[nf][1] - mn0);
                s[nf][2] = __expf(s[nf][2] - mn1);
                s[nf][3] = __expf(s[nf][3] - mn1);
                rs0 += s[nf][0] + s[nf][1];
                rs1 += s[nf][2] + s[nf][3];
            }
            #pragma unroll
            for (int off = 1; off <= 2; off <<= 1) {
                rs0 += __shfl_xor_sync(0xffffffffu, rs0, off);
                rs1 += __shfl_xor_sync(0xffffffffu, rs1, off);
            }
            float a0 = __expf(m0 - mn0), a1 = __expf(m1 - mn1);
            l0 = l0 * a0 + rs0; m0 = mn0;
            l1 = l1 * a1 + rs1; m1 = mn1;
            #pragma unroll
            for (int nf = 0; nf < 8; nf++) {
                o[nf][0] *= a0; o[nf][1] *= a0;
                o[nf][2] *= a1; o[nf][3] *= a1;
            }

            // ---- O += P . V (3-term split; P A-frags via quad shuffles) ----
            const int src1 = g * 4 + (tg >> 1);
            const int src2 = src1 + 2;
            const bool e = tg & 1;
            #pragma unroll
            for (int ksi = 0; ksi < 8; ksi++) {
                float p00 = __shfl_sync(0xffffffffu, s[ksi][0], src1);
                float p01 = __shfl_sync(0xffffffffu, s[ksi][1], src1);
                float r0 = e ? p01 : p00;
                float p10 = __shfl_sync(0xffffffffu, s[ksi][2], src1);
                float p11 = __shfl_sync(0xffffffffu, s[ksi][3], src1);
                float r1 = e ? p11 : p10;
                float p20 = __shfl_sync(0xffffffffu, s[ksi][0], src2);
                float p21 = __shfl_sync(0xffffffffu, s[ksi][1], src2);
                float r2 = e ? p21 : p20;
                float p30 = __shfl_sync(0xffffffffu, s[ksi][2], src2);
                float p31 = __shfl_sync(0xffffffffu, s[ksi][3], src2);
                float r3 = e ? p31 : p30;

                float h0 = tf32_round(r0), h1 = tf32_round(r1);
                float h2 = tf32_round(r2), h3 = tf32_round(r3);
                uint32_t ah[4] = {__float_as_uint(h0), __float_as_uint(h1),
                                  __float_as_uint(h2), __float_as_uint(h3)};
                uint32_t al[4] = {__float_as_uint(tf32_round(r0 - h0)),
                                  __float_as_uint(tf32_round(r1 - h1)),
                                  __float_as_uint(tf32_round(r2 - h2)),
                                  __float_as_uint(tf32_round(r3 - h3))};

                uint32_t bh[8][2], bl[8][2];
                #pragma unroll
                for (int nf = 0; nf < 8; nf++) {
                    int a = (ksi * 8 + tg) * VST + nf * 8 + g;
                    bh[nf][0] = __float_as_uint(vh[a]);
                    bh[nf][1] = __float_as_uint(vh[a + 4 * VST]);
                    bl[nf][0] = __float_as_uint(vl[a]);
                    bl[nf][1] = __float_as_uint(vl[a + 4 * VST]);
                }
                #pragma unroll
                for (int nf = 0; nf < 8; nf++)
                    mma_tf32(o[nf], ah, bh[nf]);
                #pragma unroll
                for (int nf = 0; nf < 8; nf++)
                    mma_tf32(o[nf], ah, bl[nf]);
                #pragma unroll
                for (int nf = 0; nf < 8; nf++)
                    mma_tf32(o[nf], al, bh[nf]);
            }
            __syncthreads();
        }

        float inv0 = 1.0f / l0, inv1 = 1.0f / l1;
        #pragma unroll
        for (int nf = 0; nf < 8; nf++) {
            int col = nf * 8 + 2 * tg;
            long r0 = base + (long)(q0 + rw) * Hn + col;
            *(float2*)&out[r0]          = make_float2(o[nf][0] * inv0, o[nf][1] * inv0);
            *(float2*)&out[r0 + 8 * Hn] = make_float2(o[nf][2] * inv1, o[nf][3] * inv1);
        }
    }
}

// ---------------------------------------------------------------------------
extern "C" void kernel_launch(void* const* d_in, const int* in_sizes, int n_in,
                              void* d_out, int out_size)
{
    const float* x  = (const float*)d_in[0];
    const float* Wk = (const float*)d_in[1];
    const float* bk = (const float*)d_in[2];
    const float* Wq = (const float*)d_in[3];
    const float* bq = (const float*)d_in[4];
    const float* Wv = (const float*)d_in[5];
    const float* bv = (const float*)d_in[6];
    float* out = (float*)d_out;

    prep_w<<<(3 * Hn * Cn) / 256, 256>>>(Wk, Wq, Wv);

    cudaFuncSetAttribute(qkv_mma, cudaFuncAttributeMaxDynamicSharedMemorySize, QKV_SMEM);
    qkv_mma<<<(Bn * Tn) / 128, 256, QKV_SMEM>>>(x, bk, bq, bv);

    cudaFuncSetAttribute(attn_mma, cudaFuncAttributeMaxDynamicSharedMemorySize, ATTN_SMEM);
    attn_mma<<<dim3(16, Bn), 128, ATTN_SMEM>>>(out);
}

// round 8
// speedup vs baseline: 3.7842x; 1.5237x over previous
#include <cuda_runtime.h>
#include <cstdint>
#include <math.h>

#define Bn 8
#define Tn 2048
#define Cn 1024
#define Hn 64

// ---------------- device scratch (sanctioned no-alloc path) ----------------
__device__ float g_q[Bn * Tn * Hn];
__device__ float g_k[Bn * Tn * Hn];
__device__ float g_v[Bn * Tn * Hn];                 // V fp32 [b][t][h]
__device__ unsigned short g_vht[Bn * Hn * Tn];      // V bf16 hi, transposed [b][h][t]
__device__ unsigned short g_vlt[Bn * Hn * Tn];      // V bf16 lo, transposed
__device__ unsigned short g_wt_hi[3 * Hn * Cn];     // W bf16 hi, [o*64+n][k]
__device__ unsigned short g_wt_lo[3 * Hn * Cn];     // W bf16 lo

__device__ __forceinline__ float tf32_round(float x) {
    uint32_t u;
    asm("cvt.rna.tf32.f32 %0, %1;" : "=r"(u) : "f"(x));
    return __uint_as_float(u);
}
__device__ __forceinline__ uint32_t bfpack(float hi, float lo) {
    uint32_t d;
    asm("cvt.rn.bf16x2.f32 %0, %1, %2;" : "=r"(d) : "f"(hi), "f"(lo));
    return d;   // d = {hi16 = bf16(hi), lo16 = bf16(lo)}
}
__device__ __forceinline__ uint32_t smem_u32(const void* p) {
    uint32_t a;
    asm("{ .reg .u64 t; cvta.to.shared.u64 t, %1; cvt.u32.u64 %0, t; }" : "=r"(a) : "l"(p));
    return a;
}
__device__ __forceinline__ void cp16(uint32_t s, const void* g) {
    asm volatile("cp.async.cg.shared.global [%0], [%1], 16;" :: "r"(s), "l"(g));
}
#define CP_COMMIT() asm volatile("cp.async.commit_group;" ::: "memory")
#define CP_WAIT1()  asm volatile("cp.async.wait_group 1;" ::: "memory")
#define CP_WAIT0()  asm volatile("cp.async.wait_group 0;" ::: "memory")

// tf32 m16n8k8 (layouts validated R3-R7)
__device__ __forceinline__ void mma_tf32(float* c, const uint32_t* a, const uint32_t* b) {
    asm volatile(
        "mma.sync.aligned.m16n8k8.row.col.f32.tf32.tf32.f32 "
        "{%0,%1,%2,%3}, {%4,%5,%6,%7}, {%8,%9}, {%0,%1,%2,%3};"
        : "+f"(c[0]), "+f"(c[1]), "+f"(c[2]), "+f"(c[3])
        : "r"(a[0]), "r"(a[1]), "r"(a[2]), "r"(a[3]), "r"(b[0]), "r"(b[1]));
}
// bf16 m16n8k16: a0=(g,2tg:2tg+1) a1=(g+8,..) a2=(g,2tg+8:2tg+9) a3=(g+8,..)
// b0=(k=2tg:2tg+1,n=g) b1=(k=2tg+8:2tg+9,n=g); C layout same as tf32.
__device__ __forceinline__ void mma_bf16(float* c, const uint32_t* a, const uint32_t* b) {
    asm volatile(
        "mma.sync.aligned.m16n8k16.row.col.f32.bf16.bf16.f32 "
        "{%0,%1,%2,%3}, {%4,%5,%6,%7}, {%8,%9}, {%0,%1,%2,%3};"
        : "+f"(c[0]), "+f"(c[1]), "+f"(c[2]), "+f"(c[3])
        : "r"(a[0]), "r"(a[1]), "r"(a[2]), "r"(a[3]), "r"(b[0]), "r"(b[1]));
}

// ---------------------------------------------------------------------------
// prep: transpose weights to [o][n][k], bf16 Dekker split.
// ---------------------------------------------------------------------------
__global__ void prep_w(const float* __restrict__ Wk, const float* __restrict__ Wq,
                       const float* __restrict__ Wv) {
    int idx = blockIdx.x * 256 + threadIdx.x;
    int o = idx / (Hn * Cn);
    int rem = idx - o * (Hn * Cn);
    int n = rem / Cn;
    int k = rem - n * Cn;
    const float* W = (o == 0) ? Wq : (o == 1) ? Wk : Wv;
    float v = W[k * Hn + n];
    uint32_t p = bfpack(v, v);
    float fb = __uint_as_float(p & 0xFFFF0000u);
    uint32_t pl = bfpack(v - fb, v - fb);
    g_wt_hi[idx] = (unsigned short)(p >> 16);
    g_wt_lo[idx] = (unsigned short)(pl >> 16);
}

// ---------------------------------------------------------------------------
// V transpose + bf16 split: g_v [t][h] f32 -> g_vht/g_vlt [h][t] bf16.
// ---------------------------------------------------------------------------
__global__ __launch_bounds__(128) void vt_split() {
    __shared__ float ts[64][65];
    const int b = blockIdx.y, t0 = blockIdx.x * 64;
    const int t = threadIdx.x;
    const float* vin = &g_v[((size_t)b * Tn + t0) * Hn];
    #pragma unroll
    for (int i = 0; i < 8; i++) {
        int c = t + i * 128;                 // 1024 float4s
        int r = c >> 4, c4 = (c & 15) * 4;
        float4 v = *(const float4*)&vin[r * Hn + c4];
        ts[r][c4] = v.x; ts[r][c4 + 1] = v.y; ts[r][c4 + 2] = v.z; ts[r][c4 + 3] = v.w;
    }
    __syncthreads();
    #pragma unroll
    for (int i = 0; i < 16; i++) {
        int c = t + i * 128;                 // 2048 u32 outputs
        int h = c >> 5, c2 = (c & 31) * 2;
        float v0 = ts[c2][h], v1 = ts[c2 + 1][h];
        uint32_t ph = bfpack(v1, v0);
        float f0 = __uint_as_float(ph << 16);
        float f1 = __uint_as_float(ph & 0xFFFF0000u);
        uint32_t pl = bfpack(v1 - f1, v0 - f0);
        size_t o = (size_t)(b * Hn + h) * Tn + t0 + c2;
        *(uint32_t*)&g_vht[o] = ph;
        *(uint32_t*)&g_vlt[o] = pl;
    }
}

// ---------------------------------------------------------------------------
// QKV via mma.sync bf16 k16, 3-term split, cp.async double-buffered.
// Stage: A f32 128x40 (20480 B) + Bh/Bl bf16 192x40 (15360 B each) = 51200 B.
// ---------------------------------------------------------------------------
#define QAST 40
#define QKV_STAGE_B 51200
#define QKV_SMEM (2 * QKV_STAGE_B)

__global__ __launch_bounds__(256) void qkv_mma(
    const float* __restrict__ x,
    const float* __restrict__ bk, const float* __restrict__ bq, const float* __restrict__ bv)
{
    extern __shared__ char smc[];
    const uint32_t sb = smem_u32(smc);
    const int t = threadIdx.x;
    const int wid = t >> 5, lane = t & 31;
    const int wm = wid >> 2, wn = wid & 3;
    const int g = lane >> 2, tg = lane & 3;
    const int m0 = blockIdx.x * 128;

    float c[4][6][4];
    #pragma unroll
    for (int mf = 0; mf < 4; mf++)
        #pragma unroll
        for (int nf = 0; nf < 6; nf++)
            #pragma unroll
            for (int r = 0; r < 4; r++) c[mf][nf][r] = 0.0f;

    auto issue = [&](int ch, int st) {
        const int k0 = ch * 32;
        uint32_t sA = sb + (uint32_t)st * QKV_STAGE_B;
        uint32_t sBh = sA + 20480;
        uint32_t sBl = sBh + 15360;
        #pragma unroll
        for (int i = 0; i < 4; i++) {
            int cc = t + i * 256;            // 1024 chunks: 128 rows x 8
            int r = cc >> 3, o = cc & 7;
            cp16(sA + r * 160 + o * 16, &x[(size_t)(m0 + r) * Cn + k0 + o * 4]);
        }
        #pragma unroll
        for (int i = 0; i < 3; i++) {
            int cc = t + i * 256;            // 768 chunks: 192 rows x 4
            int r = cc >> 2, o = cc & 3;
            cp16(sBh + r * 80 + o * 16,
                 (const char*)g_wt_hi + ((size_t)r * Cn + k0 + o * 8) * 2);
            cp16(sBl + r * 80 + o * 16,
                 (const char*)g_wt_lo + ((size_t)r * Cn + k0 + o * 8) * 2);
        }
    };

    issue(0, 0);
    CP_COMMIT();

    for (int ch = 0; ch < 32; ch++) {
        if (ch < 31) { issue(ch + 1, (ch + 1) & 1); CP_COMMIT(); CP_WAIT1(); }
        else         { CP_WAIT0(); }
        __syncthreads();

        char* stg = smc + (ch & 1) * QKV_STAGE_B;
        const float* As = (const float*)stg;
        const uint32_t* Bhu = (const uint32_t*)(stg + 20480);
        const uint32_t* Blu = (const uint32_t*)(stg + 35840);

        #pragma unroll
        for (int ks = 0; ks < 2; ks++) {
            const int kk = ks * 16;
            uint32_t a_h[4][4], a_l[4][4], b_h[6][2], b_l[6][2];
            #pragma unroll
            for (int mf = 0; mf < 4; mf++) {
                int row = wm * 64 + mf * 16 + g;
                float2 p0 = *(const float2*)&As[row * QAST + kk + 2 * tg];
                float2 p1 = *(const float2*)&As[(row + 8) * QAST + kk + 2 * tg];
                float2 p2 = *(const float2*)&As[row * QAST + kk + 8 + 2 * tg];
                float2 p3 = *(const float2*)&As[(row + 8) * QAST + kk + 8 + 2 * tg];
                float2 ps[4] = {p0, p1, p2, p3};
                #pragma unroll
                for (int q = 0; q < 4; q++) {
                    uint32_t ph = bfpack(ps[q].y, ps[q].x);
                    a_h[mf][q] = ph;
                    float f0 = __uint_as_float(ph << 16);
                    float f1 = __uint_as_float(ph & 0xFFFF0000u);
                    a_l[mf][q] = bfpack(ps[q].y - f1, ps[q].x - f0);
                }
            }
            #pragma unroll
            for (int nf = 0; nf < 6; nf++) {
                int n = wn * 48 + nf * 8 + g;
                int ab = n * 20 + ks * 8 + tg;
                b_h[nf][0] = Bhu[ab];
                b_h[nf][1] = Bhu[ab + 4];
                b_l[nf][0] = Blu[ab];
                b_l[nf][1] = Blu[ab + 4];
            }
            #pragma unroll
            for (int nf = 0; nf < 6; nf++)
                #pragma unroll
                for (int mf = 0; mf < 4; mf++)
                    mma_bf16(c[mf][nf], a_h[mf], b_h[nf]);
            #pragma unroll
            for (int nf = 0; nf < 6; nf++)
                #pragma unroll
                for (int mf = 0; mf < 4; mf++)
                    mma_bf16(c[mf][nf], a_h[mf], b_l[nf]);
            #pragma unroll
            for (int nf = 0; nf < 6; nf++)
                #pragma unroll
                for (int mf = 0; mf < 4; mf++)
                    mma_bf16(c[mf][nf], a_l[mf], b_h[nf]);
        }
        __syncthreads();
    }

    // epilogue: bias; q,k,v all fp32 (V handled by vt_split)
    #pragma unroll
    for (int nf = 0; nf < 6; nf++) {
        int col = wn * 48 + nf * 8 + tg * 2;
        int o = col >> 6;
        int h = col & 63;
        float* gout = (o == 0) ? g_q : (o == 1) ? g_k : g_v;
        const float* bias = (o == 0) ? bq : (o == 1) ? bk : bv;
        float2 bb = *(const float2*)&bias[h];
        #pragma unroll
        for (int mf = 0; mf < 4; mf++) {
            int r0 = m0 + wm * 64 + mf * 16 + g;
            *(float2*)&gout[(size_t)r0 * Hn + h] =
                make_float2(c[mf][nf][0] + bb.x, c[mf][nf][1] + bb.y);
            *(float2*)&gout[(size_t)(r0 + 8) * Hn + h] =
                make_float2(c[mf][nf][2] + bb.x, c[mf][nf][3] + bb.y);
        }
    }
}

// ---------------------------------------------------------------------------
// Flash attention: S = tf32 k8 (Q regs, K raw f32), PV = bf16 k16 3-term with
// THREAD-LOCAL P packing (C-frag == A-frag layout identity; no shuffles).
// Stage: K 64x68 f32 (17408) + VhT 64x36 u32 (9216) + VlT (9216) = 35840 B.
// ---------------------------------------------------------------------------
#define KST 68
#define ATT_STAGE_B 35840
#define ATTN_SMEM (2 * ATT_STAGE_B)

__global__ __launch_bounds__(128, 2) void attn_mma(float* __restrict__ out)
{
    extern __shared__ char smc[];
    const uint32_t sb = smem_u32(smc);

    const int t = threadIdx.x;
    const int w = t >> 5, lane = t & 31;
    const int g = lane >> 2, tg = lane & 3;
    const int b = blockIdx.y;
    const long base = (long)b * Tn * Hn;
    const float scale = 0.03125f;     // 1024^-0.5

    auto issue = [&](int k0, int st) {
        uint32_t sK = sb + (uint32_t)st * ATT_STAGE_B;
        uint32_t sVh = sK + 17408;
        uint32_t sVl = sVh + 9216;
        #pragma unroll
        for (int i = 0; i < 8; i++) {
            int r = (t >> 4) + i * 8;
            int c4 = (t & 15) * 4;
            cp16(sK + (r * KST + c4) * 4, &g_k[base + (long)(k0 + r) * Hn + c4]);
        }
        #pragma unroll
        for (int i = 0; i < 4; i++) {
            int cc = t + i * 128;            // 512 chunks: 64 h-rows x 8
            int h = cc >> 3, o = cc & 7;
            size_t go = ((size_t)(b * Hn + h) * Tn + k0 + o * 8) * 2;
            cp16(sVh + h * 144 + o * 16, (const char*)g_vht + go);
            cp16(sVl + h * 144 + o * 16, (const char*)g_vlt + go);
        }
    };

    for (int tloop = 0; tloop < 2; tloop++) {
        const int qi = (tloop == 0) ? blockIdx.x : (31 - blockIdx.x);
        const int q0 = qi * 64;
        const int rw = w * 16 + g;

        issue(0, 0);
        CP_COMMIT();

        uint32_t qa[8][4];
        {
            const float* qp = &g_q[base + (long)(q0 + rw) * Hn];
            #pragma unroll
            for (int ksi = 0; ksi < 8; ksi++) {
                qa[ksi][0] = __float_as_uint(tf32_round(qp[ksi * 8 + tg] * scale));
                qa[ksi][1] = __float_as_uint(tf32_round(qp[8 * Hn + ksi * 8 + tg] * scale));
                qa[ksi][2] = __float_as_uint(tf32_round(qp[ksi * 8 + tg + 4] * scale));
                qa[ksi][3] = __float_as_uint(tf32_round(qp[8 * Hn + ksi * 8 + tg + 4] * scale));
            }
        }

        float m0 = -1e30f, m1 = -1e30f, l0 = 0.0f, l1 = 0.0f;
        float o[8][4];
        #pragma unroll
        for (int nf = 0; nf < 8; nf++)
            #pragma unroll
            for (int r = 0; r < 4; r++) o[nf][r] = 0.0f;

        for (int j = 0; j <= qi; j++) {
            if (j < qi) { issue((j + 1) * 64, (j + 1) & 1); CP_COMMIT(); CP_WAIT1(); }
            else        { CP_WAIT0(); }
            __syncthreads();

            char* stg = smc + (j & 1) * ATT_STAGE_B;
            const float* ksm = (const float*)stg;
            const uint32_t* vhu = (const uint32_t*)(stg + 17408);
            const uint32_t* vlu = (const uint32_t*)(stg + 26624);

            // ---- S = Qs . K^T (tf32; K truncated by HW) ----
            float s[8][4];
            #pragma unroll
            for (int nf = 0; nf < 8; nf++)
                #pragma unroll
                for (int r = 0; r < 4; r++) s[nf][r] = 0.0f;

            #pragma unroll
            for (int ksi = 0; ksi < 8; ksi++) {
                uint32_t bf[8][2];
                #pragma unroll
                for (int nf = 0; nf < 8; nf++) {
                    int a = (nf * 8 + g) * KST + ksi * 8 + tg;
                    bf[nf][0] = __float_as_uint(ksm[a]);
                    bf[nf][1] = __float_as_uint(ksm[a + 4]);
                }
                #pragma unroll
                for (int nf = 0; nf < 8; nf++)
                    mma_tf32(s[nf], qa[ksi], bf[nf]);
            }

            if (j == qi) {
                #pragma unroll
                for (int nf = 0; nf < 8; nf++) {
                    int col = nf * 8 + 2 * tg;
                    if (col     > rw)     s[nf][0] = -1e30f;
                    if (col + 1 > rw)     s[nf][1] = -1e30f;
                    if (col     > rw + 8) s[nf][2] = -1e30f;
                    if (col + 1 > rw + 8) s[nf][3] = -1e30f;
                }
            }

            // ---- online softmax (rows rw, rw+8) ----
            float mx0 = -1e30f, mx1 = -1e30f;
            #pragma unroll
            for (int nf = 0; nf < 8; nf++) {
                mx0 = fmaxf(mx0, fmaxf(s[nf][0], s[nf][1]));
                mx1 = fmaxf(mx1, fmaxf(s[nf][2], s[nf][3]));
            }
            #pragma unroll
            for (int off = 1; off <= 2; off <<= 1) {
                mx0 = fmaxf(mx0, __shfl_xor_sync(0xffffffffu, mx0, off));
                mx1 = fmaxf(mx1, __shfl_xor_sync(0xffffffffu, mx1, off));
            }
            float mn0 = fmaxf(m0, mx0), mn1 = fmaxf(m1, mx1);
            float rs0 = 0.0f, rs1 = 0.0f;
            #pragma unroll
            for (int nf = 0; nf < 8; nf++) {
                s[nf][0] = __expf(s[nf][0] - mn0);
                s[nf][1] = __expf(s[nf][1] - mn0);
                s[nf][2] = __expf(s[nf][2] - mn1);
                s[nf][3] = __expf(s[nf][3] - mn1);
                rs0 += s[nf][0] + s[nf][1];
                rs1 += s[nf][2] + s[nf][3];
            }
            #pragma unroll
            for (int off = 1; off <= 2; off <<= 1) {
                rs0 += __shfl_xor_sync(0xffffffffu, rs0, off);
                rs1 += __shfl_xor_sync(0xffffffffu, rs1, off);
            }
            float a0 = __expf(m0 - mn0), a1 = __expf(m1 - mn1);
            l0 = l0 * a0 + rs0; m0 = mn0;
            l1 = l1 * a1 + rs1; m1 = mn1;
            #pragma unroll
            for (int nf = 0; nf < 8; nf++) {
                o[nf][0] *= a0; o[nf][1] *= a0;
                o[nf][2] *= a1; o[nf][3] *= a1;
            }

            // ---- O += P . V  (bf16 k16, 3 terms; A-frags packed in-place) ----
            #pragma unroll
            for (int ksi = 0; ksi < 4; ksi++) {
                uint32_t ah[4], al[4];
                #pragma unroll
                for (int q = 0; q < 4; q++) {
                    int sn = 2 * ksi + (q >> 1);
                    int e = (q & 1) * 2;
                    float s0 = s[sn][e], s1 = s[sn][e + 1];
                    uint32_t ph = bfpack(s1, s0);
                    ah[q] = ph;
                    float f0 = __uint_as_float(ph << 16);
                    float f1 = __uint_as_float(ph & 0xFFFF0000u);
                    al[q] = bfpack(s1 - f1, s0 - f0);
                }
                uint32_t bh[8][2], bl[8][2];
                #pragma unroll
                for (int nf = 0; nf < 8; nf++) {
                    int ab = (nf * 8 + g) * 36 + 8 * ksi + tg;
                    bh[nf][0] = vhu[ab];
                    bh[nf][1] = vhu[ab + 4];
                    bl[nf][0] = vlu[ab];
                    bl[nf][1] = vlu[ab + 4];
                }
                #pragma unroll
                for (int nf = 0; nf < 8; nf++)
                    mma_bf16(o[nf], ah, bh[nf]);
                #pragma unroll
                for (int nf = 0; nf < 8; nf++)
                    mma_bf16(o[nf], ah, bl[nf]);
                #pragma unroll
                for (int nf = 0; nf < 8; nf++)
                    mma_bf16(o[nf], al, bh[nf]);
            }
            __syncthreads();
        }

        float inv0 = 1.0f / l0, inv1 = 1.0f / l1;
        #pragma unroll
        for (int nf = 0; nf < 8; nf++) {
            int col = nf * 8 + 2 * tg;
            long r0 = base + (long)(q0 + rw) * Hn + col;
            *(float2*)&out[r0]          = make_float2(o[nf][0] * inv0, o[nf][1] * inv0);
            *(float2*)&out[r0 + 8 * Hn] = make_float2(o[nf][2] * inv1, o[nf][3] * inv1);
        }
    }
}

// ---------------------------------------------------------------------------
extern "C" void kernel_launch(void* const* d_in, const int* in_sizes, int n_in,
                              void* d_out, int out_size)
{
    const float* x  = (const float*)d_in[0];
    const float* Wk = (const float*)d_in[1];
    const float* bk = (const float*)d_in[2];
    const float* Wq = (const float*)d_in[3];
    const float* bq = (const float*)d_in[4];
    const float* Wv = (const float*)d_in[5];
    const float* bv = (const float*)d_in[6];
    float* out = (float*)d_out;

    prep_w<<<(3 * Hn * Cn) / 256, 256>>>(Wk, Wq, Wv);

    cudaFuncSetAttribute(qkv_mma, cudaFuncAttributeMaxDynamicSharedMemorySize, QKV_SMEM);
    qkv_mma<<<(Bn * Tn) / 128, 256, QKV_SMEM>>>(x, bk, bq, bv);

    vt_split<<<dim3(Tn / 64, Bn), 128>>>();

    cudaFuncSetAttribute(attn_mma, cudaFuncAttributeMaxDynamicSharedMemorySize, ATTN_SMEM);
    attn_mma<<<dim3(16, Bn), 128, ATTN_SMEM>>>(out);
}